// round 1
// baseline (speedup 1.0000x reference)
#include <cuda_runtime.h>
#include <math.h>

#define BB  2
#define LL  2048
#define DD  1024
#define HH  16
#define DHD 64
#define FFD 4096
#define MTOT (BB*LL)          // 4096 rows

// ---------------- scratch (static device globals; no allocation) -------------
__device__ float g_h [(size_t)MTOT*DD];    // LN1 output, later reused for (o@wo+bo+x)
__device__ float g_q [(size_t)MTOT*DD];
__device__ float g_k [(size_t)MTOT*DD];
__device__ float g_v [(size_t)MTOT*DD];
__device__ float g_o [(size_t)MTOT*DD];    // attention output
__device__ float g_y [(size_t)MTOT*DD];    // LN2 output
__device__ float g_ff[(size_t)MTOT*FFD];   // FFN hidden
__device__ float g_psum[BB*1024];
__device__ float g_psq [BB*1024];
__device__ float g_mu  [BB];
__device__ float g_rstd[BB];

// ---------------- LayerNorm over (L,D) jointly per batch ---------------------
__global__ void ln_partial(const float* __restrict__ x) {
    int b = blockIdx.y, blk = blockIdx.x;                 // 1024 blocks per batch
    const float4* xb = (const float4*)x + (size_t)b*(LL*DD/4) + (size_t)blk*512;
    float s = 0.f, sq = 0.f;
    for (int i = threadIdx.x; i < 512; i += 256) {
        float4 v = xb[i];
        s  += v.x + v.y + v.z + v.w;
        sq += v.x*v.x + v.y*v.y + v.z*v.z + v.w*v.w;
    }
    __shared__ float ss[256], ssq[256];
    ss[threadIdx.x] = s; ssq[threadIdx.x] = sq;
    __syncthreads();
    for (int st = 128; st > 0; st >>= 1) {
        if (threadIdx.x < st) { ss[threadIdx.x] += ss[threadIdx.x+st]; ssq[threadIdx.x] += ssq[threadIdx.x+st]; }
        __syncthreads();
    }
    if (threadIdx.x == 0) { g_psum[b*1024+blk] = ss[0]; g_psq[b*1024+blk] = ssq[0]; }
}

__global__ void ln_finalize() {
    int b = blockIdx.x, tid = threadIdx.x;
    float s = 0.f, sq = 0.f;
    for (int i = tid; i < 1024; i += 256) { s += g_psum[b*1024+i]; sq += g_psq[b*1024+i]; }
    __shared__ float ss[256], ssq[256];
    ss[tid] = s; ssq[tid] = sq;
    __syncthreads();
    for (int st = 128; st > 0; st >>= 1) {
        if (tid < st) { ss[tid] += ss[tid+st]; ssq[tid] += ssq[tid+st]; }
        __syncthreads();
    }
    if (tid == 0) {
        float n   = (float)LL * (float)DD;
        float mu  = ss[0] / n;
        float var = ssq[0] / n - mu*mu;
        g_mu[b]   = mu;
        g_rstd[b] = rsqrtf(var + 1e-5f);
    }
}

__global__ void ln_apply(const float* __restrict__ in, float* __restrict__ out) {
    int i = blockIdx.x*256 + threadIdx.x;                 // float4 index, 1,048,576 total
    int b = (i >= (LL*DD/4)) ? 1 : 0;
    float mu = g_mu[b], r = g_rstd[b];
    float4 v = ((const float4*)in)[i];
    v.x = (v.x-mu)*r; v.y = (v.y-mu)*r; v.z = (v.z-mu)*r; v.w = (v.w-mu)*r;
    ((float4*)out)[i] = v;
}

// ---------------- fp32 GEMM: C[m,n] = sum_k A[m,k]*W[n,k] + bias[n] (+resid)(relu)
__global__ __launch_bounds__(256) void gemm_kernel(
    const float* __restrict__ A, const float* __restrict__ W,
    const float* __restrict__ bias, const float* __restrict__ resid,
    float* __restrict__ C, int M, int N, int K, int relu)
{
    __shared__ float As[16][132];
    __shared__ float Bs[16][132];
    const int tid = threadIdx.x;
    const int tx = tid & 15, ty = tid >> 4;
    const int m0 = blockIdx.y * 128, n0 = blockIdx.x * 128;
    const float* Ab = A + (size_t)m0 * K;
    const float* Wb = W + (size_t)n0 * K;

    float acc[8][8];
    #pragma unroll
    for (int i = 0; i < 8; i++)
        #pragma unroll
        for (int j = 0; j < 8; j++) acc[i][j] = 0.f;

    for (int k0 = 0; k0 < K; k0 += 16) {
        #pragma unroll
        for (int t = tid; t < 512; t += 256) {
            int row = t >> 2;
            int kk  = (t & 3) << 2;
            float4 a = *(const float4*)(Ab + (size_t)row*K + k0 + kk);
            As[kk+0][row] = a.x; As[kk+1][row] = a.y; As[kk+2][row] = a.z; As[kk+3][row] = a.w;
            float4 w = *(const float4*)(Wb + (size_t)row*K + k0 + kk);
            Bs[kk+0][row] = w.x; Bs[kk+1][row] = w.y; Bs[kk+2][row] = w.z; Bs[kk+3][row] = w.w;
        }
        __syncthreads();
        #pragma unroll
        for (int k = 0; k < 16; k++) {
            float4 a0 = *(const float4*)&As[k][ty*4];
            float4 a1 = *(const float4*)&As[k][64 + ty*4];
            float4 b0 = *(const float4*)&Bs[k][tx*4];
            float4 b1 = *(const float4*)&Bs[k][64 + tx*4];
            float ra[8] = {a0.x,a0.y,a0.z,a0.w, a1.x,a1.y,a1.z,a1.w};
            float rb[8] = {b0.x,b0.y,b0.z,b0.w, b1.x,b1.y,b1.z,b1.w};
            #pragma unroll
            for (int i = 0; i < 8; i++)
                #pragma unroll
                for (int j = 0; j < 8; j++)
                    acc[i][j] = fmaf(ra[i], rb[j], acc[i][j]);
        }
        __syncthreads();
    }

    #pragma unroll
    for (int i = 0; i < 8; i++) {
        int m = m0 + ((i < 4) ? (ty*4 + i) : (64 + ty*4 + (i-4)));
        #pragma unroll
        for (int jg = 0; jg < 2; jg++) {
            int n = n0 + jg*64 + tx*4;
            float4 r;
            r.x = acc[i][jg*4+0] + bias[n+0];
            r.y = acc[i][jg*4+1] + bias[n+1];
            r.z = acc[i][jg*4+2] + bias[n+2];
            r.w = acc[i][jg*4+3] + bias[n+3];
            if (resid) {
                float4 rv = *(const float4*)(resid + (size_t)m*N + n);
                r.x += rv.x; r.y += rv.y; r.z += rv.z; r.w += rv.w;
            }
            if (relu) {
                r.x = fmaxf(r.x, 0.f); r.y = fmaxf(r.y, 0.f);
                r.z = fmaxf(r.z, 0.f); r.w = fmaxf(r.w, 0.f);
            }
            *(float4*)(C + (size_t)m*N + n) = r;
        }
    }
}

// ---------------- attention: O = softmax(Q K^T * 0.25) V, per (b,h) ----------
// Block: 64 q-rows of one (b,h). 256 threads as 16x16; each owns 4x4 tiles.
#define TQS 68   // row stride for Qt/Kt  (transposed: [kk][row])
#define TPS 65   // row stride for Pt     (transposed: [c][r])
#define TVS 68   // row stride for Vs     (natural:    [c][d])

__global__ __launch_bounds__(256) void attn_kernel(
    const float* __restrict__ Q, const float* __restrict__ Km,
    const float* __restrict__ V, float* __restrict__ O)
{
    extern __shared__ float sm[];
    float* Qt = sm;                  // 64*TQS
    float* Kt = Qt + 64*TQS;         // 64*TQS
    float* Pt = Kt + 64*TQS;         // 64*TPS
    float* Vs = Pt + 64*TPS;         // 64*TVS

    const int tid = threadIdx.x;
    const int sx = tid & 15, sy = tid >> 4;
    const int q0 = blockIdx.x * 64;
    const int h  = blockIdx.y, b = blockIdx.z;
    const size_t base = ((size_t)b*LL)*DD + (size_t)h*DHD;
    const float* Qb = Q  + base + (size_t)q0*DD;
    const float* Kb = Km + base;
    const float* Vb = V  + base;

    // load Q tile transposed: Qt[kk][row]
    #pragma unroll
    for (int t = tid; t < 1024; t += 256) {
        int row = t >> 4;
        int c4  = (t & 15) << 2;
        float4 v = *(const float4*)(Qb + (size_t)row*DD + c4);
        Qt[(c4+0)*TQS + row] = v.x;
        Qt[(c4+1)*TQS + row] = v.y;
        Qt[(c4+2)*TQS + row] = v.z;
        Qt[(c4+3)*TQS + row] = v.w;
    }

    float acc[4][4];
    #pragma unroll
    for (int i = 0; i < 4; i++)
        #pragma unroll
        for (int j = 0; j < 4; j++) acc[i][j] = 0.f;
    float mrow[4], lrow[4];
    #pragma unroll
    for (int i = 0; i < 4; i++) { mrow[i] = -1e30f; lrow[i] = 0.f; }

    for (int kt = 0; kt < LL; kt += 64) {
        __syncthreads();   // protects Kt/Vs/Pt reuse (and first-iter Q stores)
        #pragma unroll
        for (int t = tid; t < 1024; t += 256) {
            int row = t >> 4;
            int c4  = (t & 15) << 2;
            float4 kv = *(const float4*)(Kb + (size_t)(kt+row)*DD + c4);
            Kt[(c4+0)*TQS + row] = kv.x;
            Kt[(c4+1)*TQS + row] = kv.y;
            Kt[(c4+2)*TQS + row] = kv.z;
            Kt[(c4+3)*TQS + row] = kv.w;
            float4 vv = *(const float4*)(Vb + (size_t)(kt+row)*DD + c4);
            *(float4*)&Vs[row*TVS + c4] = vv;
        }
        __syncthreads();

        // S[4][4]: rows sy*4+i, cols sx*4+j
        float s[4][4];
        #pragma unroll
        for (int i = 0; i < 4; i++)
            #pragma unroll
            for (int j = 0; j < 4; j++) s[i][j] = 0.f;
        #pragma unroll 4
        for (int kk = 0; kk < 64; kk++) {
            float4 qa = *(const float4*)&Qt[kk*TQS + sy*4];
            float4 kb = *(const float4*)&Kt[kk*TQS + sx*4];
            float ra[4] = {qa.x,qa.y,qa.z,qa.w};
            float rb[4] = {kb.x,kb.y,kb.z,kb.w};
            #pragma unroll
            for (int i = 0; i < 4; i++)
                #pragma unroll
                for (int j = 0; j < 4; j++)
                    s[i][j] = fmaf(ra[i], rb[j], s[i][j]);
        }

        // online softmax (scale = 1/sqrt(H) = 0.25, faithful to source bug)
        #pragma unroll
        for (int i = 0; i < 4; i++) {
            #pragma unroll
            for (int j = 0; j < 4; j++) s[i][j] *= 0.25f;
            float tm = fmaxf(fmaxf(s[i][0], s[i][1]), fmaxf(s[i][2], s[i][3]));
            #pragma unroll
            for (int off = 1; off < 16; off <<= 1)
                tm = fmaxf(tm, __shfl_xor_sync(0xffffffffu, tm, off));
            float mnew = fmaxf(mrow[i], tm);
            float corr = __expf(mrow[i] - mnew);
            float rsum = 0.f;
            float p[4];
            #pragma unroll
            for (int j = 0; j < 4; j++) { p[j] = __expf(s[i][j] - mnew); rsum += p[j]; }
            #pragma unroll
            for (int off = 1; off < 16; off <<= 1)
                rsum += __shfl_xor_sync(0xffffffffu, rsum, off);
            lrow[i] = lrow[i]*corr + rsum;
            mrow[i] = mnew;
            #pragma unroll
            for (int j = 0; j < 4; j++) {
                acc[i][j] *= corr;
                Pt[(sx*4+j)*TPS + sy*4+i] = p[j];
            }
        }
        __syncthreads();

        // acc += P @ V  (P transposed in smem: Pt[c][r])
        #pragma unroll 4
        for (int c = 0; c < 64; c++) {
            float4 vb = *(const float4*)&Vs[c*TVS + sx*4];
            float pa0 = Pt[c*TPS + sy*4+0];
            float pa1 = Pt[c*TPS + sy*4+1];
            float pa2 = Pt[c*TPS + sy*4+2];
            float pa3 = Pt[c*TPS + sy*4+3];
            acc[0][0] = fmaf(pa0, vb.x, acc[0][0]); acc[0][1] = fmaf(pa0, vb.y, acc[0][1]);
            acc[0][2] = fmaf(pa0, vb.z, acc[0][2]); acc[0][3] = fmaf(pa0, vb.w, acc[0][3]);
            acc[1][0] = fmaf(pa1, vb.x, acc[1][0]); acc[1][1] = fmaf(pa1, vb.y, acc[1][1]);
            acc[1][2] = fmaf(pa1, vb.z, acc[1][2]); acc[1][3] = fmaf(pa1, vb.w, acc[1][3]);
            acc[2][0] = fmaf(pa2, vb.x, acc[2][0]); acc[2][1] = fmaf(pa2, vb.y, acc[2][1]);
            acc[2][2] = fmaf(pa2, vb.z, acc[2][2]); acc[2][3] = fmaf(pa2, vb.w, acc[2][3]);
            acc[3][0] = fmaf(pa3, vb.x, acc[3][0]); acc[3][1] = fmaf(pa3, vb.y, acc[3][1]);
            acc[3][2] = fmaf(pa3, vb.z, acc[3][2]); acc[3][3] = fmaf(pa3, vb.w, acc[3][3]);
        }
    }

    // write O rows q0+sy*4+i, head dims sx*4..sx*4+3
    float* Ob = O + base + (size_t)q0*DD;
    #pragma unroll
    for (int i = 0; i < 4; i++) {
        float inv = 1.0f / lrow[i];
        float4 o4 = make_float4(acc[i][0]*inv, acc[i][1]*inv, acc[i][2]*inv, acc[i][3]*inv);
        *(float4*)(Ob + (size_t)(sy*4+i)*DD + sx*4) = o4;
    }
}

#define ATT_SMEM_BYTES ((3*64*TQS + 64*TPS) > (2*64*TQS + 64*TPS + 64*TVS) ? 0 : 0)
static const int kAttSmem = (int)((2*64*TQS + 64*TPS + 64*TVS) * sizeof(float)); // 68,864 B

// ---------------- launcher ---------------------------------------------------
extern "C" void kernel_launch(void* const* d_in, const int* in_sizes, int n_in,
                              void* d_out, int out_size) {
    const float* x  = (const float*)d_in[0];
    const float* wq = (const float*)d_in[1];
    const float* bq = (const float*)d_in[2];
    const float* wk = (const float*)d_in[3];
    const float* bk = (const float*)d_in[4];
    const float* wv = (const float*)d_in[5];
    const float* bv = (const float*)d_in[6];
    const float* wo = (const float*)d_in[7];
    const float* bo = (const float*)d_in[8];
    const float* w1 = (const float*)d_in[9];
    const float* b1 = (const float*)d_in[10];
    const float* w2 = (const float*)d_in[11];
    const float* b2 = (const float*)d_in[12];
    float* out = (float*)d_out;

    cudaFuncSetAttribute((const void*)attn_kernel,
                         cudaFuncAttributeMaxDynamicSharedMemorySize, kAttSmem);

    void *ph, *pq, *pk, *pv, *po, *py, *pff;
    cudaGetSymbolAddress(&ph,  g_h);
    cudaGetSymbolAddress(&pq,  g_q);
    cudaGetSymbolAddress(&pk,  g_k);
    cudaGetSymbolAddress(&pv,  g_v);
    cudaGetSymbolAddress(&po,  g_o);
    cudaGetSymbolAddress(&py,  g_y);
    cudaGetSymbolAddress(&pff, g_ff);
    float* h  = (float*)ph;
    float* q  = (float*)pq;
    float* k  = (float*)pk;
    float* v  = (float*)pv;
    float* o  = (float*)po;
    float* y  = (float*)py;
    float* ff = (float*)pff;

    dim3 gRed(1024, BB);
    dim3 gProj(DD/128,  MTOT/128);   // (8, 32)
    dim3 gFF1 (FFD/128, MTOT/128);   // (32, 32)
    dim3 gAtt (LL/64, HH, BB);       // (32, 16, 2)

    // LN1
    ln_partial<<<gRed, 256>>>(x);
    ln_finalize<<<BB, 256>>>();
    ln_apply<<<4096, 256>>>(x, h);
    // QKV projections
    gemm_kernel<<<gProj, 256>>>(h, wq, bq, nullptr, q, MTOT, DD, DD, 0);
    gemm_kernel<<<gProj, 256>>>(h, wk, bk, nullptr, k, MTOT, DD, DD, 0);
    gemm_kernel<<<gProj, 256>>>(h, wv, bv, nullptr, v, MTOT, DD, DD, 0);
    // attention
    attn_kernel<<<gAtt, 256, kAttSmem>>>(q, k, v, o);
    // output projection + residual (x) -> reuse g_h as pre-LN2 tensor
    gemm_kernel<<<gProj, 256>>>(o, wo, bo, x, h, MTOT, DD, DD, 0);
    // LN2
    ln_partial<<<gRed, 256>>>(h);
    ln_finalize<<<BB, 256>>>();
    ln_apply<<<4096, 256>>>(h, y);
    // FFN
    gemm_kernel<<<gFF1, 256>>>(y, w1, b1, nullptr, ff, MTOT, FFD, DD, 1);
    gemm_kernel<<<gProj, 256>>>(ff, w2, b2, x, out, MTOT, DD, FFD, 0);
}

// round 9
// speedup vs baseline: 1.7855x; 1.7855x over previous
#include <cuda_runtime.h>
#include <cuda_bf16.h>
#include <cstdint>
#include <math.h>

#define BB  2
#define LL  2048
#define DD  1024
#define HH  16
#define DHD 64
#define FFD 4096
#define MTOT (BB*LL)          // 4096 rows

// ---------------- scratch (static device globals; no allocation) -------------
__device__ float g_h [(size_t)MTOT*DD];    // pre-LN2 tensor (o@wo+bo+x)
__device__ float g_q [(size_t)MTOT*DD];
__device__ float g_k [(size_t)MTOT*DD];
__device__ float g_v [(size_t)MTOT*DD];
__device__ float g_o [(size_t)MTOT*DD];    // attention output
__device__ float g_ff[(size_t)MTOT*FFD];   // FFN hidden
__device__ float g_psum[BB*1024];
__device__ float g_psq [BB*1024];
__device__ float g_mu  [BB];
__device__ float g_rstd[BB];

// bf16 hi/lo activation scratch (sized for largest: ff 4096x4096)
__device__ __nv_bfloat16 g_ah[(size_t)MTOT*FFD];
__device__ __nv_bfloat16 g_al[(size_t)MTOT*FFD];
// bf16 hi/lo weights: wq@0, wk@1M, wv@2M, wo@3M, w1@4M(4M), w2@8M(4M)
#define WOFF_Q  ((size_t)0)
#define WOFF_K  ((size_t)1024*1024)
#define WOFF_V  ((size_t)2*1024*1024)
#define WOFF_O  ((size_t)3*1024*1024)
#define WOFF_1  ((size_t)4*1024*1024)
#define WOFF_2  ((size_t)8*1024*1024)
__device__ __nv_bfloat16 g_wh[(size_t)12*1024*1024];
__device__ __nv_bfloat16 g_wl[(size_t)12*1024*1024];

// ======================= PTX helpers (baseline ISA, no 'a' features) =========
__device__ __forceinline__ uint32_t smem_u32(const void* p) {
    uint32_t a;
    asm("{ .reg .u64 t; cvta.to.shared.u64 t, %1; cvt.u32.u64 %0, t; }" : "=r"(a) : "l"(p));
    return a;
}
#define SWZ128(o) ((o) ^ (((o) >> 3) & 0x70))

#define CP_ASYNC16(dst, src) \
    asm volatile("cp.async.cg.shared.global [%0], [%1], 16;" :: "r"(dst), "l"(src))
#define CP_COMMIT() asm volatile("cp.async.commit_group;" ::: "memory")
#define CP_WAIT(n)  asm volatile("cp.async.wait_group %0;" :: "n"(n) : "memory")

__device__ __forceinline__ void ldsm_x4(uint32_t* r, uint32_t addr) {
    asm volatile("ldmatrix.sync.aligned.m8n8.x4.shared.b16 {%0,%1,%2,%3}, [%4];"
        : "=r"(r[0]), "=r"(r[1]), "=r"(r[2]), "=r"(r[3]) : "r"(addr));
}
__device__ __forceinline__ void mma16816(float* c, const uint32_t* a, const uint32_t* b) {
    asm volatile(
        "mma.sync.aligned.m16n8k16.row.col.f32.bf16.bf16.f32 "
        "{%0,%1,%2,%3}, {%4,%5,%6,%7}, {%8,%9}, {%0,%1,%2,%3};"
        : "+f"(c[0]), "+f"(c[1]), "+f"(c[2]), "+f"(c[3])
        : "r"(a[0]), "r"(a[1]), "r"(a[2]), "r"(a[3]), "r"(b[0]), "r"(b[1]));
}

// ---------------- LayerNorm over (L,D) jointly per batch ---------------------
__global__ void ln_partial(const float* __restrict__ x) {
    int b = blockIdx.y, blk = blockIdx.x;
    const float4* xb = (const float4*)x + (size_t)b*(LL*DD/4) + (size_t)blk*512;
    float s = 0.f, sq = 0.f;
    for (int i = threadIdx.x; i < 512; i += 256) {
        float4 v = xb[i];
        s  += v.x + v.y + v.z + v.w;
        sq += v.x*v.x + v.y*v.y + v.z*v.z + v.w*v.w;
    }
    __shared__ float ss[256], ssq[256];
    ss[threadIdx.x] = s; ssq[threadIdx.x] = sq;
    __syncthreads();
    for (int st = 128; st > 0; st >>= 1) {
        if (threadIdx.x < st) { ss[threadIdx.x] += ss[threadIdx.x+st]; ssq[threadIdx.x] += ssq[threadIdx.x+st]; }
        __syncthreads();
    }
    if (threadIdx.x == 0) { g_psum[b*1024+blk] = ss[0]; g_psq[b*1024+blk] = ssq[0]; }
}

__global__ void ln_finalize() {
    int b = blockIdx.x, tid = threadIdx.x;
    float s = 0.f, sq = 0.f;
    for (int i = tid; i < 1024; i += 256) { s += g_psum[b*1024+i]; sq += g_psq[b*1024+i]; }
    __shared__ float ss[256], ssq[256];
    ss[tid] = s; ssq[tid] = sq;
    __syncthreads();
    for (int st = 128; st > 0; st >>= 1) {
        if (tid < st) { ss[tid] += ss[tid+st]; ssq[tid] += ssq[tid+st]; }
        __syncthreads();
    }
    if (tid == 0) {
        float n   = (float)LL * (float)DD;
        float mu  = ss[0] / n;
        float var = ssq[0] / n - mu*mu;
        g_mu[b]   = mu;
        g_rstd[b] = rsqrtf(var + 1e-5f);
    }
}

__device__ __forceinline__ uint32_t pack_hi(float a, float b, __nv_bfloat16& ha, __nv_bfloat16& hb) {
    ha = __float2bfloat16(a); hb = __float2bfloat16(b);
    return ((uint32_t)__bfloat16_as_ushort(hb) << 16) | (uint32_t)__bfloat16_as_ushort(ha);
}

// normalize + split into bf16 hi/lo
__global__ void ln_apply_split(const float* __restrict__ in,
                               __nv_bfloat16* __restrict__ hi, __nv_bfloat16* __restrict__ lo) {
    int i = blockIdx.x*256 + threadIdx.x;           // float4 index
    int b = (i >= (LL*DD/4)) ? 1 : 0;
    float mu = g_mu[b], r = g_rstd[b];
    float4 v = ((const float4*)in)[i];
    v.x = (v.x-mu)*r; v.y = (v.y-mu)*r; v.z = (v.z-mu)*r; v.w = (v.w-mu)*r;
    __nv_bfloat16 h0,h1,h2,h3;
    uint2 ph, pl;
    ph.x = pack_hi(v.x, v.y, h0, h1);
    ph.y = pack_hi(v.z, v.w, h2, h3);
    float r0 = v.x - __bfloat162float(h0), r1 = v.y - __bfloat162float(h1);
    float r2 = v.z - __bfloat162float(h2), r3 = v.w - __bfloat162float(h3);
    __nv_bfloat16 l0,l1,l2,l3;
    pl.x = pack_hi(r0, r1, l0, l1);
    pl.y = pack_hi(r2, r3, l2, l3);
    ((uint2*)hi)[i] = ph;
    ((uint2*)lo)[i] = pl;
}

// plain split fp32 -> bf16 hi/lo
__global__ void split_kernel(const float* __restrict__ in,
                             __nv_bfloat16* __restrict__ hi, __nv_bfloat16* __restrict__ lo, int n4) {
    int i = blockIdx.x*256 + threadIdx.x;
    if (i >= n4) return;
    float4 v = ((const float4*)in)[i];
    __nv_bfloat16 h0,h1,h2,h3;
    uint2 ph, pl;
    ph.x = pack_hi(v.x, v.y, h0, h1);
    ph.y = pack_hi(v.z, v.w, h2, h3);
    float r0 = v.x - __bfloat162float(h0), r1 = v.y - __bfloat162float(h1);
    float r2 = v.z - __bfloat162float(h2), r3 = v.w - __bfloat162float(h3);
    __nv_bfloat16 l0,l1,l2,l3;
    pl.x = pack_hi(r0, r1, l0, l1);
    pl.y = pack_hi(r2, r3, l2, l3);
    ((uint2*)hi)[i] = ph;
    ((uint2*)lo)[i] = pl;
}

// =============== mma.sync GEMM: C[m,n] = sum_k A[m,k]*W[n,k] (+bias,resid,relu)
// CTA tile 128x128, K-chunk 64 bf16, 3-stage cp.async pipeline.
// 3-split products: Ah*Bh + Ah*Bl + Al*Bh. 8 warps as 4(m) x 2(n); warp 32x64.
#define STAGES 3
#define TILEB 16384                 // one 128x64 bf16 tile (128B rows)
#define STAGE_BYTES (4*TILEB)       // Ah, Al, Bh, Bl
#define MMG_SMEM (STAGES*STAGE_BYTES + 1024)

__device__ __forceinline__ void issue_chunk(
    uint32_t sslot,
    const __nv_bfloat16* a0, const __nv_bfloat16* a1,
    const __nv_bfloat16* b0, const __nv_bfloat16* b1,
    int K, int k0, int tid)
{
    #pragma unroll
    for (int it = 0; it < 4; it++) {
        int idx = it*256 + tid;
        int row = idx >> 3, s = idx & 7;
        uint32_t off = SWZ128((uint32_t)(row*128 + s*16));
        size_t go = (size_t)row*K + k0 + s*8;
        CP_ASYNC16(sslot + off,            a0 + go);
        CP_ASYNC16(sslot + TILEB + off,    a1 + go);
        CP_ASYNC16(sslot + 2*TILEB + off,  b0 + go);
        CP_ASYNC16(sslot + 3*TILEB + off,  b1 + go);
    }
}

__global__ __launch_bounds__(256) void mm_gemm(
    const __nv_bfloat16* __restrict__ Ah, const __nv_bfloat16* __restrict__ Al,
    const __nv_bfloat16* __restrict__ Bh, const __nv_bfloat16* __restrict__ Bl,
    const float* __restrict__ bias, const float* __restrict__ resid,
    float* __restrict__ C, int M, int N, int K, int relu)
{
    extern __shared__ char smraw[];
    char* smb = (char*)(((uintptr_t)smraw + 1023) & ~(uintptr_t)1023);
    uint32_t sbase = smem_u32(smb);

    const int tid  = threadIdx.x;
    const int warp = tid >> 5, lane = tid & 31;
    const int m0 = blockIdx.y * 128, n0 = blockIdx.x * 128;
    const int wm = (warp >> 1) * 32;      // warp m offset within CTA tile
    const int wn = (warp & 1) * 64;       // warp n offset

    const __nv_bfloat16* tA0 = Ah + (size_t)m0 * K;
    const __nv_bfloat16* tA1 = Al + (size_t)m0 * K;
    const __nv_bfloat16* tB0 = Bh + (size_t)n0 * K;
    const __nv_bfloat16* tB1 = Bl + (size_t)n0 * K;

    float acc[2][8][4];
    #pragma unroll
    for (int i = 0; i < 2; i++)
        #pragma unroll
        for (int j = 0; j < 8; j++)
            #pragma unroll
            for (int q = 0; q < 4; q++) acc[i][j][q] = 0.f;

    const int nch = K >> 6;
    // prologue: stages 0,1
    issue_chunk(sbase + 0*STAGE_BYTES, tA0, tA1, tB0, tB1, K, 0, tid);
    CP_COMMIT();
    issue_chunk(sbase + 1*STAGE_BYTES, tA0, tA1, tB0, tB1, K, 64, tid);
    CP_COMMIT();

    // per-thread ldmatrix address components (constant across ks/chunks)
    const int arow  = (lane & 7) + ((lane >> 3) & 1) * 8;   // A: mats 0/1=m0-15,k0; 2/3=k+16
    const int akoff = (lane >> 4) * 16;
    const int brow  = (lane & 7) + (lane >> 4) * 8;          // B: mats 0/1=n0-7; 2/3=n8-15
    const int bkoff = ((lane >> 3) & 1) * 16;

    for (int c = 0; c < nch; c++) {
        CP_WAIT(1);
        __syncthreads();
        int cn = c + STAGES - 1;
        if (cn < nch)
            issue_chunk(sbase + (cn % STAGES)*STAGE_BYTES, tA0, tA1, tB0, tB1, K, cn*64, tid);
        CP_COMMIT();

        uint32_t sl = sbase + (c % STAGES)*STAGE_BYTES;
        #pragma unroll
        for (int ks = 0; ks < 4; ks++) {
            uint32_t ah[2][4], al[2][4];
            #pragma unroll
            for (int mf = 0; mf < 2; mf++) {
                uint32_t off = SWZ128((uint32_t)((wm + mf*16 + arow)*128 + ks*32 + akoff));
                ldsm_x4(ah[mf], sl + off);
                ldsm_x4(al[mf], sl + TILEB + off);
            }
            #pragma unroll
            for (int g = 0; g < 4; g++) {
                uint32_t bh[4], bl[4];
                uint32_t off = SWZ128((uint32_t)((wn + g*16 + brow)*128 + ks*32 + bkoff));
                ldsm_x4(bh, sl + 2*TILEB + off);
                ldsm_x4(bl, sl + 3*TILEB + off);
                #pragma unroll
                for (int mf = 0; mf < 2; mf++) {
                    mma16816(acc[mf][2*g],   ah[mf], bh);
                    mma16816(acc[mf][2*g],   ah[mf], bl);
                    mma16816(acc[mf][2*g],   al[mf], bh);
                    mma16816(acc[mf][2*g+1], ah[mf], bh + 2);
                    mma16816(acc[mf][2*g+1], ah[mf], bl + 2);
                    mma16816(acc[mf][2*g+1], al[mf], bh + 2);
                }
            }
        }
    }

    // epilogue: registers -> global, fused bias/resid/relu
    const int rbase = m0 + wm + (lane >> 2);
    const int cbase = n0 + wn + (lane & 3) * 2;
    #pragma unroll
    for (int nf = 0; nf < 8; nf++) {
        const int col = cbase + nf*8;
        float2 bv = *(const float2*)(bias + col);
        #pragma unroll
        for (int mf = 0; mf < 2; mf++) {
            int r0 = rbase + mf*16;
            #pragma unroll
            for (int half = 0; half < 2; half++) {
                int rr = r0 + half*8;
                float2 v;
                v.x = acc[mf][nf][half*2+0] + bv.x;
                v.y = acc[mf][nf][half*2+1] + bv.y;
                if (resid) {
                    float2 rv = *(const float2*)(resid + (size_t)rr*N + col);
                    v.x += rv.x; v.y += rv.y;
                }
                if (relu) { v.x = fmaxf(v.x, 0.f); v.y = fmaxf(v.y, 0.f); }
                *(float2*)(C + (size_t)rr*N + col) = v;
            }
        }
    }
}

// ---------------- attention: O = softmax(Q K^T * 0.25) V, per (b,h) ----------
#define TQS 68
#define TPS 65
#define TVS 68

__global__ __launch_bounds__(256) void attn_kernel(
    const float* __restrict__ Q, const float* __restrict__ Km,
    const float* __restrict__ V, float* __restrict__ O)
{
    extern __shared__ float smf[];
    float* Qt = smf;
    float* Kt = Qt + 64*TQS;
    float* Pt = Kt + 64*TQS;
    float* Vs = Pt + 64*TPS;

    const int tid = threadIdx.x;
    const int sx = tid & 15, sy = tid >> 4;
    const int q0 = blockIdx.x * 64;
    const int h  = blockIdx.y, b = blockIdx.z;
    const size_t base = ((size_t)b*LL)*DD + (size_t)h*DHD;
    const float* Qb = Q  + base + (size_t)q0*DD;
    const float* Kb = Km + base;
    const float* Vb = V  + base;

    #pragma unroll
    for (int t = tid; t < 1024; t += 256) {
        int row = t >> 4;
        int c4  = (t & 15) << 2;
        float4 v = *(const float4*)(Qb + (size_t)row*DD + c4);
        Qt[(c4+0)*TQS + row] = v.x;
        Qt[(c4+1)*TQS + row] = v.y;
        Qt[(c4+2)*TQS + row] = v.z;
        Qt[(c4+3)*TQS + row] = v.w;
    }

    float acc[4][4];
    #pragma unroll
    for (int i = 0; i < 4; i++)
        #pragma unroll
        for (int j = 0; j < 4; j++) acc[i][j] = 0.f;
    float mrow[4], lrow[4];
    #pragma unroll
    for (int i = 0; i < 4; i++) { mrow[i] = -1e30f; lrow[i] = 0.f; }

    for (int kt = 0; kt < LL; kt += 64) {
        __syncthreads();
        #pragma unroll
        for (int t = tid; t < 1024; t += 256) {
            int row = t >> 4;
            int c4  = (t & 15) << 2;
            float4 kv = *(const float4*)(Kb + (size_t)(kt+row)*DD + c4);
            Kt[(c4+0)*TQS + row] = kv.x;
            Kt[(c4+1)*TQS + row] = kv.y;
            Kt[(c4+2)*TQS + row] = kv.z;
            Kt[(c4+3)*TQS + row] = kv.w;
            float4 vv = *(const float4*)(Vb + (size_t)(kt+row)*DD + c4);
            *(float4*)&Vs[row*TVS + c4] = vv;
        }
        __syncthreads();

        float s[4][4];
        #pragma unroll
        for (int i = 0; i < 4; i++)
            #pragma unroll
            for (int j = 0; j < 4; j++) s[i][j] = 0.f;
        #pragma unroll 4
        for (int kk = 0; kk < 64; kk++) {
            float4 qa = *(const float4*)&Qt[kk*TQS + sy*4];
            float4 kb = *(const float4*)&Kt[kk*TQS + sx*4];
            float ra[4] = {qa.x,qa.y,qa.z,qa.w};
            float rb[4] = {kb.x,kb.y,kb.z,kb.w};
            #pragma unroll
            for (int i = 0; i < 4; i++)
                #pragma unroll
                for (int j = 0; j < 4; j++)
                    s[i][j] = fmaf(ra[i], rb[j], s[i][j]);
        }

        #pragma unroll
        for (int i = 0; i < 4; i++) {
            #pragma unroll
            for (int j = 0; j < 4; j++) s[i][j] *= 0.25f;
            float tm = fmaxf(fmaxf(s[i][0], s[i][1]), fmaxf(s[i][2], s[i][3]));
            #pragma unroll
            for (int off = 1; off < 16; off <<= 1)
                tm = fmaxf(tm, __shfl_xor_sync(0xffffffffu, tm, off));
            float mnew = fmaxf(mrow[i], tm);
            float corr = __expf(mrow[i] - mnew);
            float rsum = 0.f;
            float p[4];
            #pragma unroll
            for (int j = 0; j < 4; j++) { p[j] = __expf(s[i][j] - mnew); rsum += p[j]; }
            #pragma unroll
            for (int off = 1; off < 16; off <<= 1)
                rsum += __shfl_xor_sync(0xffffffffu, rsum, off);
            lrow[i] = lrow[i]*corr + rsum;
            mrow[i] = mnew;
            #pragma unroll
            for (int j = 0; j < 4; j++) {
                acc[i][j] *= corr;
                Pt[(sx*4+j)*TPS + sy*4+i] = p[j];
            }
        }
        __syncthreads();

        #pragma unroll 4
        for (int c = 0; c < 64; c++) {
            float4 vb = *(const float4*)&Vs[c*TVS + sx*4];
            float pa0 = Pt[c*TPS + sy*4+0];
            float pa1 = Pt[c*TPS + sy*4+1];
            float pa2 = Pt[c*TPS + sy*4+2];
            float pa3 = Pt[c*TPS + sy*4+3];
            acc[0][0] = fmaf(pa0, vb.x, acc[0][0]); acc[0][1] = fmaf(pa0, vb.y, acc[0][1]);
            acc[0][2] = fmaf(pa0, vb.z, acc[0][2]); acc[0][3] = fmaf(pa0, vb.w, acc[0][3]);
            acc[1][0] = fmaf(pa1, vb.x, acc[1][0]); acc[1][1] = fmaf(pa1, vb.y, acc[1][1]);
            acc[1][2] = fmaf(pa1, vb.z, acc[1][2]); acc[1][3] = fmaf(pa1, vb.w, acc[1][3]);
            acc[2][0] = fmaf(pa2, vb.x, acc[2][0]); acc[2][1] = fmaf(pa2, vb.y, acc[2][1]);
            acc[2][2] = fmaf(pa2, vb.z, acc[2][2]); acc[2][3] = fmaf(pa2, vb.w, acc[2][3]);
            acc[3][0] = fmaf(pa3, vb.x, acc[3][0]); acc[3][1] = fmaf(pa3, vb.y, acc[3][1]);
            acc[3][2] = fmaf(pa3, vb.z, acc[3][2]); acc[3][3] = fmaf(pa3, vb.w, acc[3][3]);
        }
    }

    float* Ob = O + base + (size_t)q0*DD;
    #pragma unroll
    for (int i = 0; i < 4; i++) {
        float inv = 1.0f / lrow[i];
        float4 o4 = make_float4(acc[i][0]*inv, acc[i][1]*inv, acc[i][2]*inv, acc[i][3]*inv);
        *(float4*)(Ob + (size_t)(sy*4+i)*DD + sx*4) = o4;
    }
}

static const int kAttSmem = (int)((2*64*TQS + 64*TPS + 64*TVS) * sizeof(float));

// ---------------- launcher ---------------------------------------------------
extern "C" void kernel_launch(void* const* d_in, const int* in_sizes, int n_in,
                              void* d_out, int out_size) {
    const float* x  = (const float*)d_in[0];
    const float* wq = (const float*)d_in[1];
    const float* bq = (const float*)d_in[2];
    const float* wk = (const float*)d_in[3];
    const float* bk = (const float*)d_in[4];
    const float* wv = (const float*)d_in[5];
    const float* bv = (const float*)d_in[6];
    const float* wo = (const float*)d_in[7];
    const float* bo = (const float*)d_in[8];
    const float* w1 = (const float*)d_in[9];
    const float* b1 = (const float*)d_in[10];
    const float* w2 = (const float*)d_in[11];
    const float* b2 = (const float*)d_in[12];
    float* out = (float*)d_out;

    cudaFuncSetAttribute((const void*)attn_kernel,
                         cudaFuncAttributeMaxDynamicSharedMemorySize, kAttSmem);
    cudaFuncSetAttribute((const void*)mm_gemm,
                         cudaFuncAttributeMaxDynamicSharedMemorySize, MMG_SMEM);

    void *ph, *pq, *pk, *pv, *po, *pff, *pah, *pal, *pwh, *pwl;
    cudaGetSymbolAddress(&ph,  g_h);
    cudaGetSymbolAddress(&pq,  g_q);
    cudaGetSymbolAddress(&pk,  g_k);
    cudaGetSymbolAddress(&pv,  g_v);
    cudaGetSymbolAddress(&po,  g_o);
    cudaGetSymbolAddress(&pff, g_ff);
    cudaGetSymbolAddress(&pah, g_ah);
    cudaGetSymbolAddress(&pal, g_al);
    cudaGetSymbolAddress(&pwh, g_wh);
    cudaGetSymbolAddress(&pwl, g_wl);
    float* h  = (float*)ph;
    float* q  = (float*)pq;
    float* k  = (float*)pk;
    float* v  = (float*)pv;
    float* o  = (float*)po;
    float* ff = (float*)pff;
    __nv_bfloat16* ah = (__nv_bfloat16*)pah;
    __nv_bfloat16* al = (__nv_bfloat16*)pal;
    __nv_bfloat16* wh = (__nv_bfloat16*)pwh;
    __nv_bfloat16* wl = (__nv_bfloat16*)pwl;

    dim3 gRed(1024, BB);
    dim3 gProj(DD/128,  MTOT/128);   // (8, 32)
    dim3 gFF1 (FFD/128, MTOT/128);   // (32, 32)
    dim3 gAtt (LL/64, HH, BB);

    // weight splits (hi/lo bf16), every launch — deterministic
    split_kernel<<<1024, 256>>>(wq, wh + WOFF_Q, wl + WOFF_Q, 262144);
    split_kernel<<<1024, 256>>>(wk, wh + WOFF_K, wl + WOFF_K, 262144);
    split_kernel<<<1024, 256>>>(wv, wh + WOFF_V, wl + WOFF_V, 262144);
    split_kernel<<<1024, 256>>>(wo, wh + WOFF_O, wl + WOFF_O, 262144);
    split_kernel<<<4096, 256>>>(w1, wh + WOFF_1, wl + WOFF_1, 1048576);
    split_kernel<<<4096, 256>>>(w2, wh + WOFF_2, wl + WOFF_2, 1048576);

    // LN1 -> bf16 hi/lo activations
    ln_partial<<<gRed, 256>>>(x);
    ln_finalize<<<BB, 256>>>();
    ln_apply_split<<<4096, 256>>>(x, ah, al);
    // QKV projections (warp MMA)
    mm_gemm<<<gProj, 256, MMG_SMEM>>>(ah, al, wh + WOFF_Q, wl + WOFF_Q, bq, nullptr, q, MTOT, DD, DD, 0);
    mm_gemm<<<gProj, 256, MMG_SMEM>>>(ah, al, wh + WOFF_K, wl + WOFF_K, bk, nullptr, k, MTOT, DD, DD, 0);
    mm_gemm<<<gProj, 256, MMG_SMEM>>>(ah, al, wh + WOFF_V, wl + WOFF_V, bv, nullptr, v, MTOT, DD, DD, 0);
    // attention (fp32 SIMT)
    attn_kernel<<<gAtt, 256, kAttSmem>>>(q, k, v, o);
    // output projection + residual(x) -> h
    split_kernel<<<4096, 256>>>(o, ah, al, 1048576);
    mm_gemm<<<gProj, 256, MMG_SMEM>>>(ah, al, wh + WOFF_O, wl + WOFF_O, bo, x, h, MTOT, DD, DD, 0);
    // LN2 -> bf16 hi/lo
    ln_partial<<<gRed, 256>>>(h);
    ln_finalize<<<BB, 256>>>();
    ln_apply_split<<<4096, 256>>>(h, ah, al);
    // FFN
    mm_gemm<<<gFF1, 256, MMG_SMEM>>>(ah, al, wh + WOFF_1, wl + WOFF_1, b1, nullptr, ff, MTOT, FFD, DD, 1);
    split_kernel<<<16384, 256>>>(ff, ah, al, 4194304);
    mm_gemm<<<gProj, 256, MMG_SMEM>>>(ah, al, wh + WOFF_2, wl + WOFF_2, b2, x, out, MTOT, DD, FFD, 0);
}